// round 3
// baseline (speedup 1.0000x reference)
#include <cuda_runtime.h>
#include <math.h>

// Problem constants (fixed by setup_inputs)
#define NB   8
#define NQL  8192
#define NVL  16384      // 128*128
#define EDIM 256
#define NH   8
#define DH   32
#define NP   4
#define WGRID 128
#define HGRID 128

// Scratch (device globals: allocation-free per harness rules)
__device__ float g_v[(size_t)NB * NVL * EDIM];     // projected value  [B, NV, E] (E = h*32+d)
__device__ float g_mid[(size_t)NB * NQL * EDIM];   // sampled output   [B, NQ, E]

// ---------------------------------------------------------------------------
// Kernel: classic 128x128x8 fp32 SGEMM, C = A(MxK) * B(KxN) + bias(N) [+ res]
// M % 128 == 0, N % 128 == 0, K % 8 == 0 (true for all calls here)
// ---------------------------------------------------------------------------
__global__ __launch_bounds__(256) void sgemm_k(
    const float* __restrict__ A, const float* __restrict__ B,
    const float* __restrict__ bias, const float* __restrict__ res,
    float* __restrict__ C, int M, int N, int K)
{
    const int BM = 128, BN = 128, BK = 8;
    __shared__ float As[BK][BM];
    __shared__ float Bs[BK][BN];

    int tid = threadIdx.x;
    int tx = tid & 15;        // 0..15  (N micro-tile)
    int ty = tid >> 4;        // 0..15  (M micro-tile)

    int aRow = tid >> 1;           // 0..127
    int aCol = (tid & 1) * 4;      // 0 or 4
    int bRow = tid >> 5;           // 0..7
    int bCol = (tid & 31) * 4;     // 0..124

    const float* Ab = A + (size_t)blockIdx.y * BM * K;
    const float* Bb = B + blockIdx.x * BN;

    float acc[8][8];
    #pragma unroll
    for (int i = 0; i < 8; i++)
        #pragma unroll
        for (int j = 0; j < 8; j++) acc[i][j] = 0.f;

    for (int k0 = 0; k0 < K; k0 += BK) {
        float4 a4 = *(const float4*)(Ab + (size_t)aRow * K + k0 + aCol);
        As[aCol + 0][aRow] = a4.x;
        As[aCol + 1][aRow] = a4.y;
        As[aCol + 2][aRow] = a4.z;
        As[aCol + 3][aRow] = a4.w;
        *(float4*)&Bs[bRow][bCol] =
            *(const float4*)(Bb + (size_t)(k0 + bRow) * N + bCol);
        __syncthreads();

        #pragma unroll
        for (int k = 0; k < BK; k++) {
            float4 a0 = *(float4*)&As[k][ty * 8];
            float4 a1 = *(float4*)&As[k][ty * 8 + 4];
            float4 b0 = *(float4*)&Bs[k][tx * 8];
            float4 b1 = *(float4*)&Bs[k][tx * 8 + 4];
            float ar[8] = {a0.x, a0.y, a0.z, a0.w, a1.x, a1.y, a1.z, a1.w};
            float br[8] = {b0.x, b0.y, b0.z, b0.w, b1.x, b1.y, b1.z, b1.w};
            #pragma unroll
            for (int i = 0; i < 8; i++)
                #pragma unroll
                for (int j = 0; j < 8; j++) acc[i][j] += ar[i] * br[j];
        }
        __syncthreads();
    }

    #pragma unroll
    for (int i = 0; i < 8; i++) {
        size_t row = (size_t)blockIdx.y * BM + ty * 8 + i;
        #pragma unroll
        for (int j0 = 0; j0 < 8; j0 += 4) {
            int col = blockIdx.x * BN + tx * 8 + j0;
            float4 bb = *(const float4*)(bias + col);
            float4 c;
            c.x = acc[i][j0 + 0] + bb.x;
            c.y = acc[i][j0 + 1] + bb.y;
            c.z = acc[i][j0 + 2] + bb.z;
            c.w = acc[i][j0 + 3] + bb.w;
            if (res) {
                float4 r = *(const float4*)(res + row * N + col);
                c.x += r.x; c.y += r.y; c.z += r.z; c.w += r.w;
            }
            *(float4*)(C + row * N + col) = c;
        }
    }
}

// ---------------------------------------------------------------------------
// Kernel: fused offsets+attn projection (96 cols), softmax(4), bilinear sample
// Block = 256 threads, handles 16 queries of one batch.
// Phase A: logits[16][96] = Q[16][256] x [W_off | W_attn] + bias
// Phase B: warp w == head w; lane == dh channel; 16 queries per warp.
// ---------------------------------------------------------------------------
__global__ __launch_bounds__(256) void fused_sample_k(
    const float* __restrict__ Q, const float* __restrict__ ref2d,
    const float* __restrict__ Woff, const float* __restrict__ boff,
    const float* __restrict__ Wattn, const float* __restrict__ battn)
{
    __shared__ float qs[16][32];
    __shared__ float ws[32][96];
    __shared__ float lg[16][96];
    __shared__ float biasS[96];

    int tid = threadIdx.x;
    int b = blockIdx.y;
    int q0 = blockIdx.x * 16;

    if (tid < 96)
        biasS[tid] = (tid < 64) ? boff[tid] : battn[tid - 64];

    const float* Qb = Q + ((size_t)b * NQL + q0) * EDIM;

    int tq = tid >> 5;   // 0..7 : query pair group
    int tc = tid & 31;   // 0..31: column triple group

    float acc00 = 0.f, acc01 = 0.f, acc02 = 0.f;
    float acc10 = 0.f, acc11 = 0.f, acc12 = 0.f;

    for (int k0 = 0; k0 < EDIM; k0 += 32) {
        {   // stage 16x32 query chunk
            int q = tid >> 4;            // 0..15
            int c = (tid & 15) * 2;      // 0..30
            float2 v2 = *(const float2*)(Qb + (size_t)q * EDIM + k0 + c);
            qs[q][c] = v2.x; qs[q][c + 1] = v2.y;
        }
        {   // stage 32x96 weight chunk: cols 0..63 = W_off row, 64..95 = W_attn row
            int r  = tid >> 3;           // 0..31
            int c0 = (tid & 7) * 12;     // 0,12,...,84
            #pragma unroll
            for (int j = 0; j < 12; j++) {
                int c = c0 + j;
                ws[r][c] = (c < 64) ? Woff[(size_t)(k0 + r) * 64 + c]
                                    : Wattn[(size_t)(k0 + r) * 32 + (c - 64)];
            }
        }
        __syncthreads();

        #pragma unroll
        for (int k = 0; k < 32; k++) {
            float qa = qs[2 * tq][k];
            float qb2 = qs[2 * tq + 1][k];
            float w0 = ws[k][3 * tc + 0];
            float w1 = ws[k][3 * tc + 1];
            float w2 = ws[k][3 * tc + 2];
            acc00 += qa * w0;  acc01 += qa * w1;  acc02 += qa * w2;
            acc10 += qb2 * w0; acc11 += qb2 * w1; acc12 += qb2 * w2;
        }
        __syncthreads();
    }

    lg[2 * tq + 0][3 * tc + 0] = acc00 + biasS[3 * tc + 0];
    lg[2 * tq + 0][3 * tc + 1] = acc01 + biasS[3 * tc + 1];
    lg[2 * tq + 0][3 * tc + 2] = acc02 + biasS[3 * tc + 2];
    lg[2 * tq + 1][3 * tc + 0] = acc10 + biasS[3 * tc + 0];
    lg[2 * tq + 1][3 * tc + 1] = acc11 + biasS[3 * tc + 1];
    lg[2 * tq + 1][3 * tc + 2] = acc12 + biasS[3 * tc + 2];
    __syncthreads();

    // ---- Phase B: sampling. warp == head, lane == dh channel ----
    int h = tid >> 5;
    int lane = tid & 31;
    const float* vb = g_v + (size_t)b * NVL * EDIM + h * DH + lane;
    float* mb = g_mid + ((size_t)b * NQL + q0) * EDIM + h * DH + lane;

    for (int q = 0; q < 16; q++) {
        const float* rr = ref2d + ((size_t)b * NQL + q0 + q) * 2;
        float refx = __ldg(rr);
        float refy = __ldg(rr + 1);

        float l0 = lg[q][64 + h * 4 + 0];
        float l1 = lg[q][64 + h * 4 + 1];
        float l2 = lg[q][64 + h * 4 + 2];
        float l3 = lg[q][64 + h * 4 + 3];
        float m = fmaxf(fmaxf(l0, l1), fmaxf(l2, l3));
        float e0 = __expf(l0 - m), e1 = __expf(l1 - m);
        float e2 = __expf(l2 - m), e3 = __expf(l3 - m);
        float inv = 1.f / (e0 + e1 + e2 + e3);
        float aw[4] = {e0 * inv, e1 * inv, e2 * inv, e3 * inv};

        float out = 0.f;
        #pragma unroll
        for (int p = 0; p < NP; p++) {
            float offx = lg[q][h * 8 + 2 * p + 0];
            float offy = lg[q][h * 8 + 2 * p + 1];
            float locx = refx + offx * (1.0f / (float)WGRID);
            float locy = refy + offy * (1.0f / (float)HGRID);
            float x = locx * (float)WGRID - 0.5f;
            float y = locy * (float)HGRID - 0.5f;
            float x0f = floorf(x), y0f = floorf(y);
            int ix0 = (int)x0f, iy0 = (int)y0f;
            int ix1 = ix0 + 1, iy1 = iy0 + 1;
            float wx1 = x - x0f, wx0 = 1.f - wx1;
            float wy1 = y - y0f, wy0 = 1.f - wy1;

            bool vx0 = (ix0 >= 0) & (ix0 < WGRID);
            bool vx1 = (ix1 >= 0) & (ix1 < WGRID);
            bool vy0 = (iy0 >= 0) & (iy0 < HGRID);
            bool vy1 = (iy1 >= 0) & (iy1 < HGRID);

            float v00 = (vx0 & vy0) ? vb[(size_t)(iy0 * WGRID + ix0) * EDIM] : 0.f;
            float v10 = (vx1 & vy0) ? vb[(size_t)(iy0 * WGRID + ix1) * EDIM] : 0.f;
            float v01 = (vx0 & vy1) ? vb[(size_t)(iy1 * WGRID + ix0) * EDIM] : 0.f;
            float v11 = (vx1 & vy1) ? vb[(size_t)(iy1 * WGRID + ix1) * EDIM] : 0.f;

            out += aw[p] * (wy0 * (wx0 * v00 + wx1 * v10) +
                            wy1 * (wx0 * v01 + wx1 * v11));
        }
        mb[(size_t)q * EDIM] = out;
    }
}

// ---------------------------------------------------------------------------
extern "C" void kernel_launch(void* const* d_in, const int* in_sizes, int n_in,
                              void* d_out, int out_size)
{
    const float* query = (const float*)d_in[0];
    const float* value = (const float*)d_in[1];
    const float* ref2d = (const float*)d_in[2];
    // d_in[3] spatial_shapes: fixed 128x128, hardcoded
    const float* Woff  = (const float*)d_in[4];
    const float* boff  = (const float*)d_in[5];
    const float* Wattn = (const float*)d_in[6];
    const float* battn = (const float*)d_in[7];
    const float* Wval  = (const float*)d_in[8];
    const float* bval  = (const float*)d_in[9];
    const float* Wout  = (const float*)d_in[10];
    const float* bout  = (const float*)d_in[11];
    float* out = (float*)d_out;

    float *vptr, *midptr;
    cudaGetSymbolAddress((void**)&vptr, g_v);
    cudaGetSymbolAddress((void**)&midptr, g_mid);

    dim3 blk(256);

    // 1) value projection: g_v = value @ W_val + b_val   (131072 x 256 x 256)
    sgemm_k<<<dim3(EDIM / 128, (NB * NVL) / 128), blk>>>(
        value, Wval, bval, nullptr, vptr, NB * NVL, EDIM, EDIM);

    // 2) fused offset/attn projection + softmax + bilinear sampling -> g_mid
    fused_sample_k<<<dim3(NQL / 16, NB), blk>>>(
        query, ref2d, Woff, boff, Wattn, battn);

    // 3) output projection + bias + residual: out = g_mid @ W_out + b_out + query
    sgemm_k<<<dim3(EDIM / 128, (NB * NQL) / 128), blk>>>(
        midptr, Wout, bout, query, out, NB * NQL, EDIM, EDIM);
}

// round 6
// speedup vs baseline: 2.7926x; 2.7926x over previous
#include <cuda_runtime.h>
#include <cuda_bf16.h>
#include <cstdint>
#include <math.h>

// Problem constants (fixed by setup_inputs)
#define NB   8
#define NQL  8192
#define NVL  16384      // 128*128
#define EDIM 256
#define NH   8
#define DH   32
#define NP   4
#define WGRID 128
#define HGRID 128

// ---------------------------------------------------------------------------
// Device scratch (allocation-free per harness rules)
// ---------------------------------------------------------------------------
__device__ float g_v[(size_t)NB * NVL * EDIM];       // projected value  [B, NV, 256]
__device__ float g_mid[(size_t)NB * NQL * EDIM];     // sampled output   [B, NQ, 256]
__device__ float g_logit[(size_t)NB * NQL * 128];    // offsets(64)+attn(32)+pad(32)
// Packed weights, bf16 hi/lo planes, row-major [n][k]:
//   rows   0..255 : W_val   (N=256)
//   rows 256..383 : [W_off | W_attn | 0-pad]  (N=128, valid 96)
//   rows 384..639 : W_out   (N=256)
__device__ __nv_bfloat16 g_bhi[640 * 256];
__device__ __nv_bfloat16 g_blo[640 * 256];
__device__ float g_biasp[640];

// ---------------------------------------------------------------------------
// Helpers (compute_103-legal PTX only: mma.sync + ldmatrix, sm_80/75 era)
// ---------------------------------------------------------------------------
__device__ __forceinline__ uint32_t smem_u32(const void* p) {
    uint32_t a;
    asm("{ .reg .u64 t; cvta.to.shared.u64 t, %1; cvt.u32.u64 %0, t; }"
        : "=r"(a) : "l"(p));
    return a;
}

__device__ __forceinline__ void ldm_x4(uint32_t* r, uint32_t addr) {
    asm volatile("ldmatrix.sync.aligned.m8n8.x4.shared.b16 {%0,%1,%2,%3}, [%4];"
        : "=r"(r[0]), "=r"(r[1]), "=r"(r[2]), "=r"(r[3]) : "r"(addr));
}

__device__ __forceinline__ void mma16816(float* c, const uint32_t* a,
                                         const uint32_t* b) {
    asm volatile(
        "mma.sync.aligned.m16n8k16.row.col.f32.bf16.bf16.f32 "
        "{%0,%1,%2,%3}, {%4,%5,%6,%7}, {%8,%9}, {%0,%1,%2,%3};"
        : "+f"(c[0]), "+f"(c[1]), "+f"(c[2]), "+f"(c[3])
        : "r"(a[0]), "r"(a[1]), "r"(a[2]), "r"(a[3]), "r"(b[0]), "r"(b[1]));
}

// fp32 pair -> bf16x2 hi plane + bf16x2 lo (residual) plane
__device__ __forceinline__ void cvt_hilo(float x, float y,
                                         uint32_t& h, uint32_t& l) {
    __nv_bfloat162 hb, lb;
    hb.x = __float2bfloat16(x);
    hb.y = __float2bfloat16(y);
    lb.x = __float2bfloat16(x - __bfloat162float(hb.x));
    lb.y = __float2bfloat16(y - __bfloat162float(hb.y));
    h = *(uint32_t*)&hb;
    l = *(uint32_t*)&lb;
}

// ---------------------------------------------------------------------------
// Prep kernel: pack weights to bf16 hi/lo planes [n][k] + packed biases
// ---------------------------------------------------------------------------
__global__ __launch_bounds__(256) void pack_w_k(
    const float* __restrict__ Wval, const float* __restrict__ Woff,
    const float* __restrict__ Wattn, const float* __restrict__ Wout,
    const float* __restrict__ bval, const float* __restrict__ boff,
    const float* __restrict__ battn, const float* __restrict__ bout)
{
    int n = blockIdx.x;     // 0..639
    int k = threadIdx.x;    // 0..255
    float w, bv;
    if (n < 256) {
        w = Wval[(size_t)k * 256 + n];  bv = bval[n];
    } else if (n < 384) {
        int n2 = n - 256;
        w  = (n2 < 64) ? Woff[(size_t)k * 64 + n2]
                       : (n2 < 96 ? Wattn[(size_t)k * 32 + (n2 - 64)] : 0.f);
        bv = (n2 < 64) ? boff[n2] : (n2 < 96 ? battn[n2 - 64] : 0.f);
    } else {
        int n2 = n - 384;
        w = Wout[(size_t)k * 256 + n2];  bv = bout[n2];
    }
    __nv_bfloat16 h = __float2bfloat16(w);
    __nv_bfloat16 l = __float2bfloat16(w - __bfloat162float(h));
    g_bhi[(size_t)n * 256 + k] = h;
    g_blo[(size_t)n * 256 + k] = l;
    if (k == 0) g_biasp[n] = bv;
}

// ---------------------------------------------------------------------------
// HMMA GEMM: C[M, ldc](cols n0..n0+127) = A[M,256] x Wpack^T + bias [+res]
// Split-bf16: D = Ah*Bh + Ah*Bl + Al*Bh  (fp32 accumulate in C-frags)
// CTA: 256 thr = 8 warps (4M x 2N); warp tile 32x64; B slice SMEM-resident,
// reused across M-tiles (persistent grid-y stride). A streamed from gmem
// directly into fragments with on-the-fly hi/lo conversion.
// ---------------------------------------------------------------------------
#define BROW 264                     // padded bf16 elems per B smem row
#define BPLANE (128 * BROW)          // elems per plane
#define GSMEM (2 * BPLANE * 2)       // bytes (hi + lo)

__global__ __launch_bounds__(256) void hmma_gemm_k(
    const float* __restrict__ A,
    const __nv_bfloat16* __restrict__ Bhi,
    const __nv_bfloat16* __restrict__ Blo,
    const float* __restrict__ biasp,
    const float* __restrict__ res,
    float* __restrict__ C, int M, int ldc)
{
    extern __shared__ __nv_bfloat16 bsm[];   // [hi: 128 x BROW][lo: 128 x BROW]
    const int tid = threadIdx.x, lane = tid & 31, wid = tid >> 5;
    const int wm = wid & 3, wn = wid >> 2;   // warp coords: 4 x 2
    const int n0 = blockIdx.x * 128;

    // ---- stage B slice (hi/lo), row-padded for conflict-free ldmatrix ----
    {
        const uint32_t* srcH = (const uint32_t*)(Bhi + (size_t)n0 * 256);
        const uint32_t* srcL = (const uint32_t*)(Blo + (size_t)n0 * 256);
        uint32_t* dstH = (uint32_t*)bsm;
        uint32_t* dstL = (uint32_t*)(bsm + BPLANE);
        for (int i = tid; i < 128 * 128; i += 256) {
            int n = i >> 7, kk = i & 127;
            dstH[n * (BROW / 2) + kk] = srcH[i];
            dstL[n * (BROW / 2) + kk] = srcL[i];
        }
    }
    __syncthreads();

    const int g  = lane >> 2;          // row within 8-row group
    const int qc = (lane & 3) * 2;     // col pair within fragment

    // per-lane bias (cols fixed for whole kernel)
    float2 bb[8];
    #pragma unroll
    for (int j = 0; j < 8; j++)
        bb[j] = *(const float2*)(biasp + n0 + wn * 64 + j * 8 + qc);

    // ldmatrix lane address: matrix id m = lane/8, row r = lane%8
    // matrices: (n+0..7, k+0..7), (n+0..7, k+8..15), (n+8..15, k..), (n+8..15, k+8)
    const uint32_t sbase = smem_u32(bsm);
    const int lm = lane >> 3, lr = lane & 7;
    const uint32_t rowb =
        (uint32_t)((((lm >> 1) * 8 + lr) * BROW + (lm & 1) * 8) * 2);

    const int ntiles = M >> 7;
    for (int tile = blockIdx.y; tile < ntiles; tile += gridDim.y) {
        const size_t m0 = (size_t)tile << 7;
        float c[2][8][4];
        #pragma unroll
        for (int i = 0; i < 2; i++)
            #pragma unroll
            for (int j = 0; j < 8; j++)
                c[i][j][0] = c[i][j][1] = c[i][j][2] = c[i][j][3] = 0.f;

        #pragma unroll 4
        for (int ks = 0; ks < 16; ks++) {
            const int k0 = ks * 16;

            // A fragments (2 m16 tiles), gmem -> regs with hi/lo split
            uint32_t ah[2][4], al[2][4];
            #pragma unroll
            for (int i = 0; i < 2; i++) {
                const float* base =
                    A + (m0 + wm * 32 + i * 16 + g) * 256 + k0 + qc;
                float2 v0 = *(const float2*)(base);              // (g,   c)
                float2 v1 = *(const float2*)(base + 8 * 256);    // (g+8, c)
                float2 v2 = *(const float2*)(base + 8);          // (g,   c+8)
                float2 v3 = *(const float2*)(base + 8 * 256 + 8);// (g+8, c+8)
                cvt_hilo(v0.x, v0.y, ah[i][0], al[i][0]);
                cvt_hilo(v1.x, v1.y, ah[i][1], al[i][1]);
                cvt_hilo(v2.x, v2.y, ah[i][2], al[i][2]);
                cvt_hilo(v3.x, v3.y, ah[i][3], al[i][3]);
            }

            // B fragments: 8 n8-tiles, hi and lo
            uint32_t bh[8][2], bl[8][2];
            #pragma unroll
            for (int jj = 0; jj < 4; jj++) {
                uint32_t off =
                    (uint32_t)(((wn * 64 + jj * 16) * BROW + k0) * 2) + rowb;
                uint32_t r4[4];
                ldm_x4(r4, sbase + off);
                bh[2 * jj][0] = r4[0]; bh[2 * jj][1] = r4[1];
                bh[2 * jj + 1][0] = r4[2]; bh[2 * jj + 1][1] = r4[3];
                ldm_x4(r4, sbase + 2 * BPLANE + off);
                bl[2 * jj][0] = r4[0]; bl[2 * jj][1] = r4[1];
                bl[2 * jj + 1][0] = r4[2]; bl[2 * jj + 1][1] = r4[3];
            }

            // 3-pass split-bf16 MMA
            #pragma unroll
            for (int i = 0; i < 2; i++)
                #pragma unroll
                for (int j = 0; j < 8; j++) {
                    mma16816(c[i][j], ah[i], bh[j]);
                    mma16816(c[i][j], ah[i], bl[j]);
                    mma16816(c[i][j], al[i], bh[j]);
                }
        }

        // ---- epilogue: bias (+ residual) -> C ----
        #pragma unroll
        for (int i = 0; i < 2; i++) {
            size_t row = m0 + wm * 32 + i * 16 + g;
            #pragma unroll
            for (int j = 0; j < 8; j++) {
                int col = n0 + wn * 64 + j * 8 + qc;
                float2 o0, o1;
                o0.x = c[i][j][0] + bb[j].x;
                o0.y = c[i][j][1] + bb[j].y;
                o1.x = c[i][j][2] + bb[j].x;
                o1.y = c[i][j][3] + bb[j].y;
                if (res) {
                    float2 r0 = *(const float2*)(res + row * (size_t)ldc + col);
                    float2 r1 = *(const float2*)(res + (row + 8) * (size_t)ldc + col);
                    o0.x += r0.x; o0.y += r0.y;
                    o1.x += r1.x; o1.y += r1.y;
                }
                *(float2*)(C + row * (size_t)ldc + col) = o0;
                *(float2*)(C + (row + 8) * (size_t)ldc + col) = o1;
            }
        }
    }
}

// ---------------------------------------------------------------------------
// Sampler: read logits, softmax(4), bilinear gather from g_v -> g_mid
// Block = 256 threads = 8 warps, one warp per head, 16 queries per block.
// ---------------------------------------------------------------------------
__global__ __launch_bounds__(256) void sample_k(const float* __restrict__ ref2d)
{
    __shared__ float lg[16][128];
    __shared__ float refs[32];
    int tid = threadIdx.x;
    int b  = blockIdx.x >> 9;            // 512 blocks per batch
    int q0 = (blockIdx.x & 511) << 4;

    const float4* lsrc = (const float4*)(g_logit + ((size_t)b * NQL + q0) * 128);
    #pragma unroll
    for (int i = 0; i < 2; i++) {
        int f = tid + i * 256;
        ((float4*)&lg[0][0])[f] = lsrc[f];
    }
    if (tid < 32) refs[tid] = ref2d[((size_t)b * NQL + q0) * 2 + tid];
    __syncthreads();

    int h = tid >> 5, lane = tid & 31;
    const float* vb = g_v + (size_t)b * NVL * EDIM + h * DH + lane;
    float* mb = g_mid + ((size_t)b * NQL + q0) * EDIM + h * DH + lane;

    for (int q = 0; q < 16; q++) {
        float refx = refs[2 * q], refy = refs[2 * q + 1];

        float l0 = lg[q][64 + h * 4 + 0];
        float l1 = lg[q][64 + h * 4 + 1];
        float l2 = lg[q][64 + h * 4 + 2];
        float l3 = lg[q][64 + h * 4 + 3];
        float m = fmaxf(fmaxf(l0, l1), fmaxf(l2, l3));
        float e0 = __expf(l0 - m), e1 = __expf(l1 - m);
        float e2 = __expf(l2 - m), e3 = __expf(l3 - m);
        float inv = 1.f / (e0 + e1 + e2 + e3);
        float aw[4] = {e0 * inv, e1 * inv, e2 * inv, e3 * inv};

        float out = 0.f;
        #pragma unroll
        for (int p = 0; p < NP; p++) {
            float offx = lg[q][h * 8 + 2 * p + 0];
            float offy = lg[q][h * 8 + 2 * p + 1];
            float x = (refx + offx * (1.0f / (float)WGRID)) * (float)WGRID - 0.5f;
            float y = (refy + offy * (1.0f / (float)HGRID)) * (float)HGRID - 0.5f;
            float x0f = floorf(x), y0f = floorf(y);
            int ix0 = (int)x0f, iy0 = (int)y0f;
            int ix1 = ix0 + 1, iy1 = iy0 + 1;
            float wx1 = x - x0f, wx0 = 1.f - wx1;
            float wy1 = y - y0f, wy0 = 1.f - wy1;

            bool vx0 = (ix0 >= 0) & (ix0 < WGRID);
            bool vx1 = (ix1 >= 0) & (ix1 < WGRID);
            bool vy0 = (iy0 >= 0) & (iy0 < HGRID);
            bool vy1 = (iy1 >= 0) & (iy1 < HGRID);

            float v00 = (vx0 & vy0) ? vb[(size_t)(iy0 * WGRID + ix0) * EDIM] : 0.f;
            float v10 = (vx1 & vy0) ? vb[(size_t)(iy0 * WGRID + ix1) * EDIM] : 0.f;
            float v01 = (vx0 & vy1) ? vb[(size_t)(iy1 * WGRID + ix0) * EDIM] : 0.f;
            float v11 = (vx1 & vy1) ? vb[(size_t)(iy1 * WGRID + ix1) * EDIM] : 0.f;

            out += aw[p] * (wy0 * (wx0 * v00 + wx1 * v10) +
                            wy1 * (wx0 * v01 + wx1 * v11));
        }
        mb[(size_t)q * EDIM] = out;
    }
}

// ---------------------------------------------------------------------------
extern "C" void kernel_launch(void* const* d_in, const int* in_sizes, int n_in,
                              void* d_out, int out_size)
{
    const float* query = (const float*)d_in[0];
    const float* value = (const float*)d_in[1];
    const float* ref2d = (const float*)d_in[2];
    // d_in[3] spatial_shapes: fixed 128x128, hardcoded
    const float* Woff  = (const float*)d_in[4];
    const float* boff  = (const float*)d_in[5];
    const float* Wattn = (const float*)d_in[6];
    const float* battn = (const float*)d_in[7];
    const float* Wval  = (const float*)d_in[8];
    const float* bval  = (const float*)d_in[9];
    const float* Wout  = (const float*)d_in[10];
    const float* bout  = (const float*)d_in[11];
    float* out = (float*)d_out;

    float *vptr, *midptr, *lptr, *bpf;
    __nv_bfloat16 *bhip, *blop;
    cudaGetSymbolAddress((void**)&vptr,   g_v);
    cudaGetSymbolAddress((void**)&midptr, g_mid);
    cudaGetSymbolAddress((void**)&lptr,   g_logit);
    cudaGetSymbolAddress((void**)&bhip,   g_bhi);
    cudaGetSymbolAddress((void**)&blop,   g_blo);
    cudaGetSymbolAddress((void**)&bpf,    g_biasp);

    cudaFuncSetAttribute(hmma_gemm_k,
                         cudaFuncAttributeMaxDynamicSharedMemorySize, GSMEM);

    // 0) pack all weights -> bf16 hi/lo planes (+ padded biases)
    pack_w_k<<<640, 256>>>(Wval, Woff, Wattn, Wout, bval, boff, battn, bout);

    // 1) value projection: g_v = value @ W_val + b_val     (131072 x 256 x 256)
    hmma_gemm_k<<<dim3(2, 74), 256, GSMEM>>>(
        value, bhip, blop, bpf, nullptr, vptr, NB * NVL, 256);

    // 2) logits: g_logit = query @ [W_off|W_attn|0] + bias (65536 x 128 x 256)
    hmma_gemm_k<<<dim3(1, 148), 256, GSMEM>>>(
        query, bhip + 256 * 256, blop + 256 * 256, bpf + 256,
        nullptr, lptr, NB * NQL, 128);

    // 3) softmax + bilinear sampling -> g_mid
    sample_k<<<NB * NQL / 16, 256>>>(ref2d);

    // 4) output projection + bias + residual -> out        (65536 x 256 x 256)
    hmma_gemm_k<<<dim3(2, 74), 256, GSMEM>>>(
        midptr, bhip + 384 * 256, blop + 384 * 256, bpf + 384,
        query, out, NB * NQL, 256);
}

// round 9
// speedup vs baseline: 3.4258x; 1.2267x over previous
#include <cuda_runtime.h>
#include <cuda_bf16.h>
#include <cstdint>
#include <math.h>

// Problem constants (fixed by setup_inputs)
#define NB   8
#define NQL  8192
#define NVL  16384      // 128*128
#define EDIM 256
#define NH   8
#define DH   32
#define NP   4
#define WGRID 128
#define HGRID 128

// ---------------------------------------------------------------------------
// Device scratch (allocation-free per harness rules)
// ---------------------------------------------------------------------------
__device__ float g_v[(size_t)NB * NVL * EDIM];       // projected value  [B, NV, 256]
__device__ float g_mid[(size_t)NB * NQL * EDIM];     // sampled output   [B, NQ, 256]
__device__ float g_logit[(size_t)NB * NQL * 128];    // offsets(64)+attn(32)+pad(32)
// Packed weights, bf16 hi/lo planes, row-major [n][k]
__device__ __nv_bfloat16 g_bhi[640 * 256];
__device__ __nv_bfloat16 g_blo[640 * 256];
__device__ float g_biasp[640];

// ---------------------------------------------------------------------------
// Helpers (compute_103-legal PTX only: mma.sync + ldmatrix)
// ---------------------------------------------------------------------------
__device__ __forceinline__ uint32_t smem_u32(const void* p) {
    uint32_t a;
    asm("{ .reg .u64 t; cvta.to.shared.u64 t, %1; cvt.u32.u64 %0, t; }"
        : "=r"(a) : "l"(p));
    return a;
}

__device__ __forceinline__ void ldm_x4(uint32_t* r, uint32_t addr) {
    asm volatile("ldmatrix.sync.aligned.m8n8.x4.shared.b16 {%0,%1,%2,%3}, [%4];"
        : "=r"(r[0]), "=r"(r[1]), "=r"(r[2]), "=r"(r[3]) : "r"(addr));
}

__device__ __forceinline__ void mma16816(float* c, const uint32_t* a,
                                         const uint32_t* b) {
    asm volatile(
        "mma.sync.aligned.m16n8k16.row.col.f32.bf16.bf16.f32 "
        "{%0,%1,%2,%3}, {%4,%5,%6,%7}, {%8,%9}, {%0,%1,%2,%3};"
        : "+f"(c[0]), "+f"(c[1]), "+f"(c[2]), "+f"(c[3])
        : "r"(a[0]), "r"(a[1]), "r"(a[2]), "r"(a[3]), "r"(b[0]), "r"(b[1]));
}

// fp32 pair -> bf16x2 hi plane + bf16x2 lo (residual) plane (fast path)
__device__ __forceinline__ void cvt_hilo(float x, float y,
                                         uint32_t& h, uint32_t& l) {
    asm("cvt.rn.bf16x2.f32 %0, %1, %2;" : "=r"(h) : "f"(y), "f"(x)); // hi=y lo=x
    float hx = __uint_as_float(__byte_perm(0u, h, 0x5400));
    float hy = __uint_as_float(__byte_perm(0u, h, 0x7600));
    float lx = x - hx, ly = y - hy;
    asm("cvt.rn.bf16x2.f32 %0, %1, %2;" : "=r"(l) : "f"(ly), "f"(lx));
}

// ---------------------------------------------------------------------------
// Prep kernel: pack weights to bf16 hi/lo planes [n][k] + packed biases
// ---------------------------------------------------------------------------
__global__ __launch_bounds__(256) void pack_w_k(
    const float* __restrict__ Wval, const float* __restrict__ Woff,
    const float* __restrict__ Wattn, const float* __restrict__ Wout,
    const float* __restrict__ bval, const float* __restrict__ boff,
    const float* __restrict__ battn, const float* __restrict__ bout)
{
    int n = blockIdx.x;     // 0..639
    int k = threadIdx.x;    // 0..255
    float w, bv;
    if (n < 256) {
        w = Wval[(size_t)k * 256 + n];  bv = bval[n];
    } else if (n < 384) {
        int n2 = n - 256;
        w  = (n2 < 64) ? Woff[(size_t)k * 64 + n2]
                       : (n2 < 96 ? Wattn[(size_t)k * 32 + (n2 - 64)] : 0.f);
        bv = (n2 < 64) ? boff[n2] : (n2 < 96 ? battn[n2 - 64] : 0.f);
    } else {
        int n2 = n - 384;
        w = Wout[(size_t)k * 256 + n2];  bv = bout[n2];
    }
    __nv_bfloat16 h = __float2bfloat16(w);
    __nv_bfloat16 l = __float2bfloat16(w - __bfloat162float(h));
    g_bhi[(size_t)n * 256 + k] = h;
    g_blo[(size_t)n * 256 + k] = l;
    if (k == 0) g_biasp[n] = bv;
}

// ---------------------------------------------------------------------------
// HMMA GEMM: C[M, ldc](cols n0..n0+127) = A[M,256] x Wpack^T + bias [+res]
// Split-bf16: D = Ah*Bh + Ah*Bl + Al*Bh  (fp32 accumulate in C-frags)
// CTA: 256 thr = 8 warps (4M x 2N); warp tile 32x64; B slice SMEM-resident.
// A streamed from gmem with a double-buffered register prefetch pipeline.
// ---------------------------------------------------------------------------
#define BROW 264                     // padded bf16 elems per B smem row
#define BPLANE (128 * BROW)          // elems per plane
#define GSMEM (2 * BPLANE * 2)       // bytes (hi + lo)

__global__ __launch_bounds__(256) void hmma_gemm_k(
    const float* __restrict__ A,
    const __nv_bfloat16* __restrict__ Bhi,
    const __nv_bfloat16* __restrict__ Blo,
    const float* __restrict__ biasp,
    const float* __restrict__ res,
    float* __restrict__ C, int M, int ldc)
{
    extern __shared__ __nv_bfloat16 bsm[];   // [hi: 128 x BROW][lo: 128 x BROW]
    const int tid = threadIdx.x, lane = tid & 31, wid = tid >> 5;
    const int wm = wid & 3, wn = wid >> 2;   // warp coords: 4 x 2
    const int n0 = blockIdx.x * 128;

    // ---- stage B slice (hi/lo), row-padded for conflict-free ldmatrix ----
    {
        const uint32_t* srcH = (const uint32_t*)(Bhi + (size_t)n0 * 256);
        const uint32_t* srcL = (const uint32_t*)(Blo + (size_t)n0 * 256);
        uint32_t* dstH = (uint32_t*)bsm;
        uint32_t* dstL = (uint32_t*)(bsm + BPLANE);
        for (int i = tid; i < 128 * 128; i += 256) {
            int n = i >> 7, kk = i & 127;
            dstH[n * (BROW / 2) + kk] = srcH[i];
            dstL[n * (BROW / 2) + kk] = srcL[i];
        }
    }
    __syncthreads();

    const int g  = lane >> 2;          // row within 8-row group
    const int qc = (lane & 3) * 2;     // col pair within fragment

    // per-lane bias (cols fixed for whole kernel)
    float2 bb[8];
    #pragma unroll
    for (int j = 0; j < 8; j++)
        bb[j] = *(const float2*)(biasp + n0 + wn * 64 + j * 8 + qc);

    // ldmatrix lane address
    const uint32_t sbase = smem_u32(bsm);
    const int lm = lane >> 3, lr = lane & 7;
    const uint32_t rowb =
        (uint32_t)((((lm >> 1) * 8 + lr) * BROW + (lm & 1) * 8) * 2);

    const int ntiles = M >> 7;
    for (int tile = blockIdx.y; tile < ntiles; tile += gridDim.y) {
        const size_t m0 = (size_t)tile << 7;
        float c[2][8][4];
        #pragma unroll
        for (int i = 0; i < 2; i++)
            #pragma unroll
            for (int j = 0; j < 8; j++)
                c[i][j][0] = c[i][j][1] = c[i][j][2] = c[i][j][3] = 0.f;

        const float* a0 = A + (m0 + wm * 32 + g) * 256 + qc;
        const float* a1 = a0 + 16 * 256;

        float2 vbuf[2][2][4];
        // prologue: load ks=0
        {
            vbuf[0][0][0] = *(const float2*)(a0);
            vbuf[0][0][1] = *(const float2*)(a0 + 2048);
            vbuf[0][0][2] = *(const float2*)(a0 + 8);
            vbuf[0][0][3] = *(const float2*)(a0 + 2056);
            vbuf[0][1][0] = *(const float2*)(a1);
            vbuf[0][1][1] = *(const float2*)(a1 + 2048);
            vbuf[0][1][2] = *(const float2*)(a1 + 8);
            vbuf[0][1][3] = *(const float2*)(a1 + 2056);
        }

        #pragma unroll 4
        for (int ks = 0; ks < 16; ks++) {
            const int k0 = ks * 16;
            float2 (&v)[2][4] = vbuf[ks & 1];

            // prefetch next chunk into the other buffer (overlaps MMAs)
            if (ks < 15) {
                float2 (&vn)[2][4] = vbuf[(ks + 1) & 1];
                const float* p0 = a0 + k0 + 16;
                const float* p1 = a1 + k0 + 16;
                vn[0][0] = *(const float2*)(p0);
                vn[0][1] = *(const float2*)(p0 + 2048);
                vn[0][2] = *(const float2*)(p0 + 8);
                vn[0][3] = *(const float2*)(p0 + 2056);
                vn[1][0] = *(const float2*)(p1);
                vn[1][1] = *(const float2*)(p1 + 2048);
                vn[1][2] = *(const float2*)(p1 + 8);
                vn[1][3] = *(const float2*)(p1 + 2056);
            }

            // convert current A chunk -> hi/lo fragments
            uint32_t ah[2][4], al[2][4];
            #pragma unroll
            for (int i = 0; i < 2; i++) {
                cvt_hilo(v[i][0].x, v[i][0].y, ah[i][0], al[i][0]);
                cvt_hilo(v[i][1].x, v[i][1].y, ah[i][1], al[i][1]);
                cvt_hilo(v[i][2].x, v[i][2].y, ah[i][2], al[i][2]);
                cvt_hilo(v[i][3].x, v[i][3].y, ah[i][3], al[i][3]);
            }

            // B fragments: 8 n8-tiles, hi and lo
            uint32_t bh[8][2], bl[8][2];
            #pragma unroll
            for (int jj = 0; jj < 4; jj++) {
                uint32_t off =
                    (uint32_t)(((wn * 64 + jj * 16) * BROW + k0) * 2) + rowb;
                uint32_t r4[4];
                ldm_x4(r4, sbase + off);
                bh[2 * jj][0] = r4[0]; bh[2 * jj][1] = r4[1];
                bh[2 * jj + 1][0] = r4[2]; bh[2 * jj + 1][1] = r4[3];
                ldm_x4(r4, sbase + 2 * BPLANE + off);
                bl[2 * jj][0] = r4[0]; bl[2 * jj][1] = r4[1];
                bl[2 * jj + 1][0] = r4[2]; bl[2 * jj + 1][1] = r4[3];
            }

            // 3-pass split-bf16 MMA
            #pragma unroll
            for (int i = 0; i < 2; i++)
                #pragma unroll
                for (int j = 0; j < 8; j++) {
                    mma16816(c[i][j], ah[i], bh[j]);
                    mma16816(c[i][j], ah[i], bl[j]);
                    mma16816(c[i][j], al[i], bh[j]);
                }
        }

        // ---- epilogue: bias (+ residual) -> C ----
        #pragma unroll
        for (int i = 0; i < 2; i++) {
            size_t row = m0 + wm * 32 + i * 16 + g;
            #pragma unroll
            for (int j = 0; j < 8; j++) {
                int col = n0 + wn * 64 + j * 8 + qc;
                float2 o0, o1;
                o0.x = c[i][j][0] + bb[j].x;
                o0.y = c[i][j][1] + bb[j].y;
                o1.x = c[i][j][2] + bb[j].x;
                o1.y = c[i][j][3] + bb[j].y;
                if (res) {
                    float2 r0 = *(const float2*)(res + row * (size_t)ldc + col);
                    float2 r1 = *(const float2*)(res + (row + 8) * (size_t)ldc + col);
                    o0.x += r0.x; o0.y += r0.y;
                    o1.x += r1.x; o1.y += r1.y;
                }
                *(float2*)(C + row * (size_t)ldc + col) = o0;
                *(float2*)(C + (row + 8) * (size_t)ldc + col) = o1;
            }
        }
    }
}

// ---------------------------------------------------------------------------
// Sampler, two-phase:
//  setup : 256 threads precompute all 512 (q,h,p) records once per block:
//          clamped packed corner coords + softmax-folded (and validity-zeroed)
//          bilinear corner weights.
//  gather: warp = head, lane = channel; pure LDS-broadcast + LDG + FFMA.
// ---------------------------------------------------------------------------
__global__ __launch_bounds__(256) void sample_k(const float* __restrict__ ref2d)
{
    __shared__ float    lg[16][128];
    __shared__ float    refs[32];
    __shared__ uint32_t smP[512];     // [q][h][p] packed x0|y0<<8|x1<<16|y1<<24
    __shared__ float4   smW[512];     // [q][h][p] corner weights * aw[p]

    int tid = threadIdx.x;
    int b  = blockIdx.x >> 9;            // 512 blocks per batch
    int q0 = (blockIdx.x & 511) << 4;

    const float4* lsrc = (const float4*)(g_logit + ((size_t)b * NQL + q0) * 128);
    #pragma unroll
    for (int i = 0; i < 2; i++) {
        int f = tid + i * 256;
        ((float4*)&lg[0][0])[f] = lsrc[f];
    }
    if (tid < 32) refs[tid] = ref2d[((size_t)b * NQL + q0) * 2 + tid];
    __syncthreads();

    // ---- setup phase: 2 threads per (q,h) combo, 2 points each ----
    {
        int cb = tid >> 1;               // 0..127 = q*8+h
        int q  = cb >> 3, h = cb & 7;
        int pbase = (tid & 1) * 2;

        float l0 = lg[q][64 + h * 4 + 0];
        float l1 = lg[q][64 + h * 4 + 1];
        float l2 = lg[q][64 + h * 4 + 2];
        float l3 = lg[q][64 + h * 4 + 3];
        float m = fmaxf(fmaxf(l0, l1), fmaxf(l2, l3));
        float e0 = __expf(l0 - m), e1 = __expf(l1 - m);
        float e2 = __expf(l2 - m), e3 = __expf(l3 - m);
        float inv = 1.f / (e0 + e1 + e2 + e3);
        float aw[4] = {e0 * inv, e1 * inv, e2 * inv, e3 * inv};

        float refx = refs[2 * q], refy = refs[2 * q + 1];

        #pragma unroll
        for (int pp = 0; pp < 2; pp++) {
            int p = pbase + pp;
            float offx = lg[q][h * 8 + 2 * p + 0];
            float offy = lg[q][h * 8 + 2 * p + 1];
            float x = fmaf(refx, (float)WGRID, offx) - 0.5f;
            float y = fmaf(refy, (float)HGRID, offy) - 0.5f;
            float x0f = floorf(x), y0f = floorf(y);
            int ix0 = (int)x0f, iy0 = (int)y0f;
            int ix1 = ix0 + 1, iy1 = iy0 + 1;
            float wx1 = x - x0f, wx0 = 1.f - wx1;
            float wy1 = y - y0f, wy0 = 1.f - wy1;

            bool vx0 = (unsigned)ix0 < WGRID;
            bool vx1 = (unsigned)ix1 < WGRID;
            bool vy0 = (unsigned)iy0 < HGRID;
            bool vy1 = (unsigned)iy1 < HGRID;

            float ap = aw[p];
            float4 w;
            w.x = (vx0 & vy0) ? ap * wx0 * wy0 : 0.f;
            w.y = (vx1 & vy0) ? ap * wx1 * wy0 : 0.f;
            w.z = (vx0 & vy1) ? ap * wx0 * wy1 : 0.f;
            w.w = (vx1 & vy1) ? ap * wx1 * wy1 : 0.f;

            int x0c = min(max(ix0, 0), WGRID - 1);
            int x1c = min(max(ix1, 0), WGRID - 1);
            int y0c = min(max(iy0, 0), HGRID - 1);
            int y1c = min(max(iy1, 0), HGRID - 1);

            int idx = cb * 4 + p;
            smP[idx] = (uint32_t)x0c | ((uint32_t)y0c << 8) |
                       ((uint32_t)x1c << 16) | ((uint32_t)y1c << 24);
            smW[idx] = w;
        }
    }
    __syncthreads();

    // ---- gather phase ----
    int h = tid >> 5, lane = tid & 31;
    const float* vb = g_v + (size_t)b * NVL * EDIM + h * DH + lane;
    float* mb = g_mid + ((size_t)b * NQL + q0) * EDIM + h * DH + lane;

    #pragma unroll 4
    for (int q = 0; q < 16; q++) {
        int base = (q * 8 + h) * 4;
        float out = 0.f;
        #pragma unroll
        for (int p = 0; p < NP; p++) {
            uint32_t pk = smP[base + p];
            float4 w = smW[base + p];
            int x0 = pk & 255, y0 = (pk >> 8) & 255;
            int x1 = (pk >> 16) & 255, y1 = pk >> 24;
            int r0 = y0 << 7, r1 = y1 << 7;
            out = fmaf(w.x, vb[(size_t)((r0 + x0) << 8)], out);
            out = fmaf(w.y, vb[(size_t)((r0 + x1) << 8)], out);
            out = fmaf(w.z, vb[(size_t)((r1 + x0) << 8)], out);
            out = fmaf(w.w, vb[(size_t)((r1 + x1) << 8)], out);
        }
        mb[(size_t)q * EDIM] = out;
    }
}

// ---------------------------------------------------------------------------
extern "C" void kernel_launch(void* const* d_in, const int* in_sizes, int n_in,
                              void* d_out, int out_size)
{
    const float* query = (const float*)d_in[0];
    const float* value = (const float*)d_in[1];
    const float* ref2d = (const float*)d_in[2];
    // d_in[3] spatial_shapes: fixed 128x128, hardcoded
    const float* Woff  = (const float*)d_in[4];
    const float* boff  = (const float*)d_in[5];
    const float* Wattn = (const float*)d_in[6];
    const float* battn = (const float*)d_in[7];
    const float* Wval  = (const float*)d_in[8];
    const float* bval  = (const float*)d_in[9];
    const float* Wout  = (const float*)d_in[10];
    const float* bout  = (const float*)d_in[11];
    float* out = (float*)d_out;

    float *vptr, *midptr, *lptr, *bpf;
    __nv_bfloat16 *bhip, *blop;
    cudaGetSymbolAddress((void**)&vptr,   g_v);
    cudaGetSymbolAddress((void**)&midptr, g_mid);
    cudaGetSymbolAddress((void**)&lptr,   g_logit);
    cudaGetSymbolAddress((void**)&bhip,   g_bhi);
    cudaGetSymbolAddress((void**)&blop,   g_blo);
    cudaGetSymbolAddress((void**)&bpf,    g_biasp);

    cudaFuncSetAttribute(hmma_gemm_k,
                         cudaFuncAttributeMaxDynamicSharedMemorySize, GSMEM);

    // 0) pack all weights -> bf16 hi/lo planes (+ padded biases)
    pack_w_k<<<640, 256>>>(Wval, Woff, Wattn, Wout, bval, boff, battn, bout);

    // 1) value projection: g_v = value @ W_val + b_val     (131072 x 256 x 256)
    hmma_gemm_k<<<dim3(2, 74), 256, GSMEM>>>(
        value, bhip, blop, bpf, nullptr, vptr, NB * NVL, 256);

    // 2) logits: g_logit = query @ [W_off|W_attn|0] + bias (65536 x 128 x 256)
    hmma_gemm_k<<<dim3(1, 148), 256, GSMEM>>>(
        query, bhip + 256 * 256, blop + 256 * 256, bpf + 256,
        nullptr, lptr, NB * NQL, 128);

    // 3) softmax + bilinear sampling -> g_mid
    sample_k<<<NB * NQL / 16, 256>>>(ref2d);

    // 4) output projection + bias + residual -> out        (65536 x 256 x 256)
    hmma_gemm_k<<<dim3(2, 74), 256, GSMEM>>>(
        midptr, bhip + 384 * 256, blop + 384 * 256, bpf + 384,
        query, out, NB * NQL, 256);
}